// round 10
// baseline (speedup 1.0000x reference)
#include <cuda_runtime.h>
#include <cuda_bf16.h>
#include <math.h>
#include <cstdint>

#define MAXN 50000
#define NPAD 50048
#define MAXE 800000
#define DIN  256
#define HD   128
#define EPSW 1e-6f

// ---------------- scratch ----------------
__device__ __align__(16) float4 g_h4[NPAD * 32];          // h: [N][128]
__device__ float4 g_ssrc[MAXN];
__device__ float4 g_sdst[MAXN];
__device__ int    g_deg[MAXN + 1];
__device__ int    g_off[MAXN + 1];
__device__ int    g_rank[MAXE];
__device__ int    g_bsum[128];
__device__ __align__(16) int2   g_epk[MAXE];              // (src, gate bits)
__device__ __align__(16) float4 g_ep[MAXE];               // p = gate*exp(tanh) per head
__device__ __align__(16) __nv_bfloat16 g_wthi[HD * DIN];  // W^T hi: [n][k]
__device__ __align__(16) __nv_bfloat16 g_wtlo[HD * DIN];  // W^T lo: [n][k]

__device__ __forceinline__ uint32_t smem_u32(const void* p) {
    uint32_t a;
    asm("{ .reg .u64 t; cvta.to.shared.u64 t, %1; cvt.u32.u64 %0, t; }" : "=r"(a) : "l"(p));
    return a;
}
__device__ __forceinline__ void mma16816(float* d, const uint32_t* a,
                                         uint32_t b0, uint32_t b1) {
    asm volatile(
        "mma.sync.aligned.m16n8k16.row.col.f32.bf16.bf16.f32 "
        "{%0,%1,%2,%3}, {%4,%5,%6,%7}, {%8,%9}, {%0,%1,%2,%3};"
        : "+f"(d[0]), "+f"(d[1]), "+f"(d[2]), "+f"(d[3])
        : "r"(a[0]), "r"(a[1]), "r"(a[2]), "r"(a[3]), "r"(b0), "r"(b1));
}
__device__ __forceinline__ void ldmat_x4(uint32_t* f, uint32_t addr) {
    asm volatile("ldmatrix.sync.aligned.m8n8.x4.shared.b16 {%0,%1,%2,%3}, [%4];"
                 : "=r"(f[0]), "=r"(f[1]), "=r"(f[2]), "=r"(f[3]) : "r"(addr));
}

// ============ prep: W^T bf16 hi/lo + zero degree counters ============
__global__ void prep_kernel(const float* __restrict__ Wm, int Nn) {
    int i = blockIdx.x * blockDim.x + threadIdx.x;
    if (i < HD * DIN) {
        int n = i >> 8;
        int k = i & 255;
        float v = Wm[k * HD + n];
        __nv_bfloat16 hi = __float2bfloat16(v);
        float lo = v - __bfloat162float(hi);
        g_wthi[i] = hi;
        g_wtlo[i] = __float2bfloat16(lo);
    }
    if (i <= Nn) g_deg[i] = 0;
}

// ====== HMMA GEMM: h = x @ W (3-product bf16 split) + fused sdot ======
#define APITCH 72
#define TILE_B (128 * APITCH * 2)
#define SM_AH  0
#define SM_AL  (SM_AH + TILE_B)
#define SM_BH  (SM_AL + TILE_B)
#define SM_BL  (SM_BH + TILE_B)
#define SM_TOT (SM_BL + TILE_B)

__global__ void __launch_bounds__(256, 1) hmma_gemm_kernel(const float* __restrict__ x,
                                                           const float* __restrict__ a_src,
                                                           const float* __restrict__ a_dst,
                                                           int Nn) {
    extern __shared__ char smem[];
    const uint32_t sb = smem_u32(smem);
    const int tid  = threadIdx.x;
    const int wid  = tid >> 5;
    const int lane = tid & 31;
    const int wm   = wid & 3;
    const int wn   = wid >> 2;
    const int rowBase = blockIdx.x * 128;

    float acc[2][8][4];
#pragma unroll
    for (int mt = 0; mt < 2; ++mt)
#pragma unroll
        for (int nt = 0; nt < 8; ++nt)
#pragma unroll
            for (int q = 0; q < 4; ++q) acc[mt][nt][q] = 0.f;

    for (int c = 0; c < 4; ++c) {
        const int k0 = c * 64;
#pragma unroll
        for (int j = 0; j < 8; ++j) {
            int idx = j * 256 + tid;
            int r   = idx >> 4;
            int c4  = idx & 15;
            int grow = rowBase + r;
            float4 v = make_float4(0.f, 0.f, 0.f, 0.f);
            if (grow < Nn)
                v = *(const float4*)&x[(size_t)grow * DIN + k0 + c4 * 4];
            float f[4] = {v.x, v.y, v.z, v.w};
            __nv_bfloat16 hi[4], lo[4];
#pragma unroll
            for (int q = 0; q < 4; ++q) {
                hi[q] = __float2bfloat16(f[q]);
                lo[q] = __float2bfloat16(f[q] - __bfloat162float(hi[q]));
            }
            __nv_bfloat162 h0 = __halves2bfloat162(hi[0], hi[1]);
            __nv_bfloat162 h1 = __halves2bfloat162(hi[2], hi[3]);
            __nv_bfloat162 l0 = __halves2bfloat162(lo[0], lo[1]);
            __nv_bfloat162 l1 = __halves2bfloat162(lo[2], lo[3]);
            uint2 uh, ul;
            uh.x = *reinterpret_cast<uint32_t*>(&h0);
            uh.y = *reinterpret_cast<uint32_t*>(&h1);
            ul.x = *reinterpret_cast<uint32_t*>(&l0);
            ul.y = *reinterpret_cast<uint32_t*>(&l1);
            int off = r * (APITCH * 2) + c4 * 8;
            *(uint2*)(smem + SM_AH + off) = uh;
            *(uint2*)(smem + SM_AL + off) = ul;
        }
#pragma unroll
        for (int j = 0; j < 4; ++j) {
            int idx = j * 256 + tid;
            int r   = idx >> 3;
            int c16 = idx & 7;
            size_t gsrc = (size_t)r * DIN + k0 + c16 * 8;
            uint4 vh = *(const uint4*)&g_wthi[gsrc];
            uint4 vl = *(const uint4*)&g_wtlo[gsrc];
            int off = r * (APITCH * 2) + c16 * 16;
            *(uint4*)(smem + SM_BH + off) = vh;
            *(uint4*)(smem + SM_BL + off) = vl;
        }
        __syncthreads();

        const __nv_bfloat16* BsH = (const __nv_bfloat16*)(smem + SM_BH);
        const __nv_bfloat16* BsL = (const __nv_bfloat16*)(smem + SM_BL);
#pragma unroll
        for (int kk = 0; kk < 4; ++kk) {
            const int kbase = kk * 16;
            uint32_t ah[2][4], al[2][4];
            const int lr = lane & 15;
            const int lc = (lane >> 4) * 8;
#pragma unroll
            for (int mt = 0; mt < 2; ++mt) {
                int m = wm * 32 + mt * 16 + lr;
                uint32_t byteoff = (uint32_t)(m * (APITCH * 2) + (kbase + lc) * 2);
                ldmat_x4(ah[mt], sb + SM_AH + byteoff);
                ldmat_x4(al[mt], sb + SM_AL + byteoff);
            }
            const int bn = (lane >> 2);
            const int bk = kbase + (lane & 3) * 2;
#pragma unroll
            for (int nt = 0; nt < 8; ++nt) {
                int n = wn * 64 + nt * 8 + bn;
                uint32_t bh0 = *(const uint32_t*)&BsH[n * APITCH + bk];
                uint32_t bh1 = *(const uint32_t*)&BsH[n * APITCH + bk + 8];
                uint32_t bl0 = *(const uint32_t*)&BsL[n * APITCH + bk];
                uint32_t bl1 = *(const uint32_t*)&BsL[n * APITCH + bk + 8];
#pragma unroll
                for (int mt = 0; mt < 2; ++mt) {
                    mma16816(acc[mt][nt], ah[mt], bh0, bh1);
                    mma16816(acc[mt][nt], ah[mt], bl0, bl1);
                    mma16816(acc[mt][nt], al[mt], bh0, bh1);
                }
            }
        }
        __syncthreads();
    }

    // ---- epilogue 1: write h rows
    float* gh = (float*)g_h4;
    const int er = lane >> 2;            // 0..7
    const int ec = (lane & 3) * 2;       // 0,2,4,6
#pragma unroll
    for (int mt = 0; mt < 2; ++mt) {
        int r1 = rowBase + wm * 32 + mt * 16 + er;
        int r2 = r1 + 8;
#pragma unroll
        for (int nt = 0; nt < 8; ++nt) {
            int cc = wn * 64 + nt * 8 + ec;
            if (r1 < Nn)
                *(float2*)&gh[(size_t)r1 * HD + cc] =
                    make_float2(acc[mt][nt][0], acc[mt][nt][1]);
            if (r2 < Nn)
                *(float2*)&gh[(size_t)r2 * HD + cc] =
                    make_float2(acc[mt][nt][2], acc[mt][nt][3]);
        }
    }

    // ---- epilogue 2: fused sdot — per-row <h,a_src>/<h,a_dst> per head
    // smem tiles are free now (synced above); stage [128 rows][4 heads][2]
    float* sdb = (float*)smem;
    float as_v[16], ad_v[16];
#pragma unroll
    for (int nt = 0; nt < 8; ++nt) {
        int cc = wn * 64 + nt * 8 + ec;
        as_v[nt * 2]     = a_src[cc];
        as_v[nt * 2 + 1] = a_src[cc + 1];
        ad_v[nt * 2]     = a_dst[cc];
        ad_v[nt * 2 + 1] = a_dst[cc + 1];
    }
#pragma unroll
    for (int mt = 0; mt < 2; ++mt) {
        float ps[2][2] = {{0.f, 0.f}, {0.f, 0.f}};   // [half(row r1/r2)][headLocal]
        float pd[2][2] = {{0.f, 0.f}, {0.f, 0.f}};
#pragma unroll
        for (int nt = 0; nt < 8; ++nt) {
            int hl = nt >> 2;
            ps[0][hl] += acc[mt][nt][0] * as_v[nt * 2] + acc[mt][nt][1] * as_v[nt * 2 + 1];
            ps[1][hl] += acc[mt][nt][2] * as_v[nt * 2] + acc[mt][nt][3] * as_v[nt * 2 + 1];
            pd[0][hl] += acc[mt][nt][0] * ad_v[nt * 2] + acc[mt][nt][1] * ad_v[nt * 2 + 1];
            pd[1][hl] += acc[mt][nt][2] * ad_v[nt * 2] + acc[mt][nt][3] * ad_v[nt * 2 + 1];
        }
        // reduce across the 4 lanes of each column group (er fixed)
#pragma unroll
        for (int o = 1; o < 4; o <<= 1) {
#pragma unroll
            for (int hf = 0; hf < 2; ++hf)
#pragma unroll
                for (int hl = 0; hl < 2; ++hl) {
                    ps[hf][hl] += __shfl_xor_sync(0xffffffffu, ps[hf][hl], o);
                    pd[hf][hl] += __shfl_xor_sync(0xffffffffu, pd[hf][hl], o);
                }
        }
        if ((lane & 3) == 0) {
            int r0 = wm * 32 + mt * 16 + er;   // local rows r0 and r0+8
#pragma unroll
            for (int hl = 0; hl < 2; ++hl) {
                int hgl = 2 * wn + hl;
                sdb[r0 * 8 + hgl * 2 + 0]       = ps[0][hl];
                sdb[r0 * 8 + hgl * 2 + 1]       = pd[0][hl];
                sdb[(r0 + 8) * 8 + hgl * 2 + 0] = ps[1][hl];
                sdb[(r0 + 8) * 8 + hgl * 2 + 1] = pd[1][hl];
            }
        }
    }
    __syncthreads();
    if (tid < 128) {
        int grow = rowBase + tid;
        if (grow < Nn) {
            g_ssrc[grow] = make_float4(sdb[tid * 8 + 0], sdb[tid * 8 + 2],
                                       sdb[tid * 8 + 4], sdb[tid * 8 + 6]);
            g_sdst[grow] = make_float4(sdb[tid * 8 + 1], sdb[tid * 8 + 3],
                                       sdb[tid * 8 + 5], sdb[tid * 8 + 7]);
        }
    }
}

// ---------------- CSR construction ----------------
// hist also records each edge's rank within its destination bucket
__global__ void hist_kernel(const int2* __restrict__ adj, int E) {
    int e = blockIdx.x * blockDim.x + threadIdx.x;
    if (e < E) g_rank[e] = atomicAdd(&g_deg[adj[e].y], 1);
}

// parallel exclusive scan of g_deg -> g_off (3 kernels)
__global__ void scan1_kernel(int Nn) {
    __shared__ int ws[16];
    int tid = threadIdx.x, lane = tid & 31, wid = tid >> 5;
    int i = blockIdx.x * 512 + tid;
    int d = (i < Nn) ? g_deg[i] : 0;
    int v = d;
#pragma unroll
    for (int o = 1; o < 32; o <<= 1) {
        int t = __shfl_up_sync(0xffffffffu, v, o);
        if (lane >= o) v += t;
    }
    if (lane == 31) ws[wid] = v;
    __syncthreads();
    if (tid == 0) {
        int run = 0;
#pragma unroll
        for (int k = 0; k < 16; ++k) { int t = ws[k]; ws[k] = run; run += t; }
        g_bsum[blockIdx.x] = run;
    }
    __syncthreads();
    int excl = v - d + ws[wid];
    if (i < Nn) g_off[i] = excl;
}

__global__ void scan2_kernel(int NB, int Nn, int E) {
    __shared__ int ws[4];
    int tid = threadIdx.x, lane = tid & 31, wid = tid >> 5;
    int d = (tid < NB) ? g_bsum[tid] : 0;
    int v = d;
#pragma unroll
    for (int o = 1; o < 32; o <<= 1) {
        int t = __shfl_up_sync(0xffffffffu, v, o);
        if (lane >= o) v += t;
    }
    if (lane == 31) ws[wid] = v;
    __syncthreads();
    if (tid == 0) {
        int run = 0;
#pragma unroll
        for (int k = 0; k < 4; ++k) { int t = ws[k]; ws[k] = run; run += t; }
    }
    __syncthreads();
    int excl = v - d + ws[wid];
    if (tid < NB) g_bsum[tid] = excl;
    if (tid == 0) g_off[Nn] = E;
}

__global__ void scan3_kernel(int Nn) {
    int i = blockIdx.x * 512 + threadIdx.x;
    if (i < Nn) g_off[i] += g_bsum[blockIdx.x];
}

// scatter: build CSR (atomic-free via rank) and store p = gate*exp(tanh(ss+sd))
__global__ void scatter_kernel(const int2* __restrict__ adj,
                               const float* __restrict__ w, int E) {
    int e = blockIdx.x * blockDim.x + threadIdx.x;
    if (e >= E) return;
    int2 a   = adj[e];
    int  pos = g_off[a.y] + g_rank[e];
    float g  = fmaxf(w[e], EPSW);
    float4 ss = g_ssrc[a.x];
    float4 sd = g_sdst[a.y];
    float4 p;
    p.x = g * __expf(tanhf(ss.x + sd.x));
    p.y = g * __expf(tanhf(ss.y + sd.y));
    p.z = g * __expf(tanhf(ss.z + sd.z));
    p.w = g * __expf(tanhf(ss.w + sd.w));
    g_epk[pos] = make_int2(a.x, __float_as_int(g));
    g_ep[pos]  = p;
}

// ---------------- aggregation: 2 passes, one warp per dst node -----
__device__ __forceinline__ float gelu_exact(float v) {
    return 0.5f * v * (1.0f + erff(v * 0.70710678118654752f));
}

__global__ void aggregate_kernel(float* __restrict__ out, int Nn) {
    int n    = (blockIdx.x * blockDim.x + threadIdx.x) >> 5;
    int lane = threadIdx.x & 31;
    if (n >= Nn) return;

    const int start = g_off[n];
    const int end   = g_off[n + 1];

    // ---- pass A: per-head denom = sum p (streaming)
    float4 den = make_float4(0.f, 0.f, 0.f, 0.f);
    for (int i = start + lane; i < end; i += 32) {
        float4 p = g_ep[i];
        den.x += p.x;
        den.y += p.y;
        den.z += p.z;
        den.w += p.w;
    }
#pragma unroll
    for (int o = 16; o > 0; o >>= 1) {
        den.x += __shfl_xor_sync(0xffffffffu, den.x, o);
        den.y += __shfl_xor_sync(0xffffffffu, den.y, o);
        den.z += __shfl_xor_sync(0xffffffffu, den.z, o);
        den.w += __shfl_xor_sync(0xffffffffu, den.w, o);
    }

    // ---- pass B: weighted gather (lane covers dims lane*4..+3)
    const int hh = lane >> 3;
    float myDen = (hh == 0) ? den.x : (hh == 1) ? den.y : (hh == 2) ? den.z : den.w;
    float myInv = 1.0f / myDen;

    float4 acc = make_float4(0.f, 0.f, 0.f, 0.f);
    const float* ep_f = (const float*)g_ep;
#pragma unroll 2
    for (int e = start; e < end; ++e) {
        int2  ek  = g_epk[e];
        float g   = __int_as_float(ek.y);
        float pv  = ep_f[(size_t)e * 4 + hh];
        float wgt = pv * g * myInv;
        float4 hv = g_h4[(size_t)ek.x * 32 + lane];
        acc.x = fmaf(wgt, hv.x, acc.x);
        acc.y = fmaf(wgt, hv.y, acc.y);
        acc.z = fmaf(wgt, hv.z, acc.z);
        acc.w = fmaf(wgt, hv.w, acc.w);
    }

    float4 res;
    res.x = gelu_exact(acc.x);
    res.y = gelu_exact(acc.y);
    res.z = gelu_exact(acc.z);
    res.w = gelu_exact(acc.w);
    *(float4*)&out[(size_t)n * HD + lane * 4] = res;
}

// ---------------- launch ----------------
extern "C" void kernel_launch(void* const* d_in, const int* in_sizes, int n_in,
                              void* d_out, int out_size) {
    const float* x     = (const float*)d_in[0];
    const int*   adj   = (const int*)d_in[1];
    const float* w     = (const float*)d_in[2];
    const float* Wm    = (const float*)d_in[3];
    const float* a_src = (const float*)d_in[4];
    const float* a_dst = (const float*)d_in[5];
    float*       out   = (float*)d_out;

    const int Nn   = in_sizes[0] / DIN;
    const int E    = in_sizes[2];
    const int Npad = ((Nn + 127) / 128) * 128;
    const int NB   = (Nn + 511) / 512;
    const int prepN = (HD * DIN > Nn + 1) ? HD * DIN : Nn + 1;

    cudaFuncSetAttribute(hmma_gemm_kernel,
                         cudaFuncAttributeMaxDynamicSharedMemorySize, SM_TOT);

    prep_kernel<<<(prepN + 255) / 256, 256>>>(Wm, Nn);
    hmma_gemm_kernel<<<Npad / 128, 256, SM_TOT>>>(x, a_src, a_dst, Nn);
    hist_kernel<<<(E + 255) / 256, 256>>>((const int2*)adj, E);
    scan1_kernel<<<NB, 512>>>(Nn);
    scan2_kernel<<<1, 128>>>(NB, Nn, E);
    scan3_kernel<<<NB, 512>>>(Nn);
    scatter_kernel<<<(E + 255) / 256, 256>>>((const int2*)adj, w, E);
    aggregate_kernel<<<(Nn * 32 + 255) / 256, 256>>>(out, Nn);
}

// round 11
// speedup vs baseline: 1.4817x; 1.4817x over previous
#include <cuda_runtime.h>
#include <cuda_bf16.h>
#include <math.h>
#include <cstdint>

#define MAXN 50000
#define NPAD 50048
#define MAXE 800000
#define DIN  256
#define HD   128
#define EPSW 1e-6f

// ---------------- scratch ----------------
__device__ __align__(16) float4 g_h4[NPAD * 32];          // h: [N][128]
__device__ float4 g_ssrc[MAXN];
__device__ float4 g_sdst[MAXN];
__device__ int    g_deg[MAXN + 1];
__device__ int    g_off[MAXN + 1];
__device__ int    g_cur[MAXN + 1];
__device__ int    g_bsum[128];
__device__ __align__(16) int2   g_epk[MAXE];              // (src, gate bits)
__device__ __align__(16) float4 g_ep[MAXE];               // p = gate*exp(tanh) per head
__device__ __align__(16) __nv_bfloat16 g_wthi[HD * DIN];  // W^T hi: [n][k]
__device__ __align__(16) __nv_bfloat16 g_wtlo[HD * DIN];  // W^T lo: [n][k]

__device__ __forceinline__ uint32_t smem_u32(const void* p) {
    uint32_t a;
    asm("{ .reg .u64 t; cvta.to.shared.u64 t, %1; cvt.u32.u64 %0, t; }" : "=r"(a) : "l"(p));
    return a;
}
__device__ __forceinline__ void mma16816(float* d, const uint32_t* a,
                                         uint32_t b0, uint32_t b1) {
    asm volatile(
        "mma.sync.aligned.m16n8k16.row.col.f32.bf16.bf16.f32 "
        "{%0,%1,%2,%3}, {%4,%5,%6,%7}, {%8,%9}, {%0,%1,%2,%3};"
        : "+f"(d[0]), "+f"(d[1]), "+f"(d[2]), "+f"(d[3])
        : "r"(a[0]), "r"(a[1]), "r"(a[2]), "r"(a[3]), "r"(b0), "r"(b1));
}
__device__ __forceinline__ void ldmat_x4(uint32_t* f, uint32_t addr) {
    asm volatile("ldmatrix.sync.aligned.m8n8.x4.shared.b16 {%0,%1,%2,%3}, [%4];"
                 : "=r"(f[0]), "=r"(f[1]), "=r"(f[2]), "=r"(f[3]) : "r"(addr));
}

// ============ prep: W^T bf16 hi/lo + zero degree counters ============
__global__ void prep_kernel(const float* __restrict__ Wm, int Nn) {
    int i = blockIdx.x * blockDim.x + threadIdx.x;
    if (i < HD * DIN) {
        int n = i >> 8;
        int k = i & 255;
        float v = Wm[k * HD + n];
        __nv_bfloat16 hi = __float2bfloat16(v);
        float lo = v - __bfloat162float(hi);
        g_wthi[i] = hi;
        g_wtlo[i] = __float2bfloat16(lo);
    }
    if (i <= Nn) g_deg[i] = 0;
}

// =============== HMMA GEMM: h = x @ W (3-product bf16 split) ================
#define APITCH 72
#define TILE_B (128 * APITCH * 2)
#define SM_AH  0
#define SM_AL  (SM_AH + TILE_B)
#define SM_BH  (SM_AL + TILE_B)
#define SM_BL  (SM_BH + TILE_B)
#define SM_TOT (SM_BL + TILE_B)

__global__ void __launch_bounds__(256, 1) hmma_gemm_kernel(const float* __restrict__ x,
                                                           int Nn) {
    extern __shared__ char smem[];
    const uint32_t sb = smem_u32(smem);
    const int tid  = threadIdx.x;
    const int wid  = tid >> 5;
    const int lane = tid & 31;
    const int wm   = wid & 3;
    const int wn   = wid >> 2;
    const int rowBase = blockIdx.x * 128;

    float acc[2][8][4];
#pragma unroll
    for (int mt = 0; mt < 2; ++mt)
#pragma unroll
        for (int nt = 0; nt < 8; ++nt)
#pragma unroll
            for (int q = 0; q < 4; ++q) acc[mt][nt][q] = 0.f;

    for (int c = 0; c < 4; ++c) {
        const int k0 = c * 64;
#pragma unroll
        for (int j = 0; j < 8; ++j) {
            int idx = j * 256 + tid;
            int r   = idx >> 4;
            int c4  = idx & 15;
            int grow = rowBase + r;
            float4 v = make_float4(0.f, 0.f, 0.f, 0.f);
            if (grow < Nn)
                v = *(const float4*)&x[(size_t)grow * DIN + k0 + c4 * 4];
            float f[4] = {v.x, v.y, v.z, v.w};
            __nv_bfloat16 hi[4], lo[4];
#pragma unroll
            for (int q = 0; q < 4; ++q) {
                hi[q] = __float2bfloat16(f[q]);
                lo[q] = __float2bfloat16(f[q] - __bfloat162float(hi[q]));
            }
            __nv_bfloat162 h0 = __halves2bfloat162(hi[0], hi[1]);
            __nv_bfloat162 h1 = __halves2bfloat162(hi[2], hi[3]);
            __nv_bfloat162 l0 = __halves2bfloat162(lo[0], lo[1]);
            __nv_bfloat162 l1 = __halves2bfloat162(lo[2], lo[3]);
            uint2 uh, ul;
            uh.x = *reinterpret_cast<uint32_t*>(&h0);
            uh.y = *reinterpret_cast<uint32_t*>(&h1);
            ul.x = *reinterpret_cast<uint32_t*>(&l0);
            ul.y = *reinterpret_cast<uint32_t*>(&l1);
            int off = r * (APITCH * 2) + c4 * 8;
            *(uint2*)(smem + SM_AH + off) = uh;
            *(uint2*)(smem + SM_AL + off) = ul;
        }
#pragma unroll
        for (int j = 0; j < 4; ++j) {
            int idx = j * 256 + tid;
            int r   = idx >> 3;
            int c16 = idx & 7;
            size_t gsrc = (size_t)r * DIN + k0 + c16 * 8;
            uint4 vh = *(const uint4*)&g_wthi[gsrc];
            uint4 vl = *(const uint4*)&g_wtlo[gsrc];
            int off = r * (APITCH * 2) + c16 * 16;
            *(uint4*)(smem + SM_BH + off) = vh;
            *(uint4*)(smem + SM_BL + off) = vl;
        }
        __syncthreads();

        const __nv_bfloat16* BsH = (const __nv_bfloat16*)(smem + SM_BH);
        const __nv_bfloat16* BsL = (const __nv_bfloat16*)(smem + SM_BL);
#pragma unroll
        for (int kk = 0; kk < 4; ++kk) {
            const int kbase = kk * 16;
            uint32_t ah[2][4], al[2][4];
            const int lr = lane & 15;
            const int lc = (lane >> 4) * 8;
#pragma unroll
            for (int mt = 0; mt < 2; ++mt) {
                int m = wm * 32 + mt * 16 + lr;
                uint32_t byteoff = (uint32_t)(m * (APITCH * 2) + (kbase + lc) * 2);
                ldmat_x4(ah[mt], sb + SM_AH + byteoff);
                ldmat_x4(al[mt], sb + SM_AL + byteoff);
            }
            const int bn = (lane >> 2);
            const int bk = kbase + (lane & 3) * 2;
#pragma unroll
            for (int nt = 0; nt < 8; ++nt) {
                int n = wn * 64 + nt * 8 + bn;
                uint32_t bh0 = *(const uint32_t*)&BsH[n * APITCH + bk];
                uint32_t bh1 = *(const uint32_t*)&BsH[n * APITCH + bk + 8];
                uint32_t bl0 = *(const uint32_t*)&BsL[n * APITCH + bk];
                uint32_t bl1 = *(const uint32_t*)&BsL[n * APITCH + bk + 8];
#pragma unroll
                for (int mt = 0; mt < 2; ++mt) {
                    mma16816(acc[mt][nt], ah[mt], bh0, bh1);
                    mma16816(acc[mt][nt], ah[mt], bl0, bl1);
                    mma16816(acc[mt][nt], al[mt], bh0, bh1);
                }
            }
        }
        __syncthreads();
    }

    float* gh = (float*)g_h4;
    const int er = lane >> 2;
    const int ec = (lane & 3) * 2;
#pragma unroll
    for (int mt = 0; mt < 2; ++mt) {
        int r1 = rowBase + wm * 32 + mt * 16 + er;
        int r2 = r1 + 8;
#pragma unroll
        for (int nt = 0; nt < 8; ++nt) {
            int cc = wn * 64 + nt * 8 + ec;
            if (r1 < Nn)
                *(float2*)&gh[(size_t)r1 * HD + cc] =
                    make_float2(acc[mt][nt][0], acc[mt][nt][1]);
            if (r2 < Nn)
                *(float2*)&gh[(size_t)r2 * HD + cc] =
                    make_float2(acc[mt][nt][2], acc[mt][nt][3]);
        }
    }
}

// -------- per-node attention scalars (float4 loads, 8-lane reduce) --------
__global__ void sdot_kernel(const float4* __restrict__ a_src4,
                            const float4* __restrict__ a_dst4,
                            int Nn) {
    int gw   = (blockIdx.x * blockDim.x + threadIdx.x) >> 5;
    int lane = threadIdx.x & 31;
    if (gw >= Nn) return;

    float4 hv = g_h4[(size_t)gw * 32 + lane];
    float4 as = a_src4[lane];
    float4 ad = a_dst4[lane];
    float ps = hv.x * as.x + hv.y * as.y + hv.z * as.z + hv.w * as.w;
    float pd = hv.x * ad.x + hv.y * ad.y + hv.z * ad.z + hv.w * ad.w;
#pragma unroll
    for (int o = 1; o < 8; o <<= 1) {
        ps += __shfl_xor_sync(0xffffffffu, ps, o);
        pd += __shfl_xor_sync(0xffffffffu, pd, o);
    }
    float s0 = __shfl_sync(0xffffffffu, ps, 0);
    float s1 = __shfl_sync(0xffffffffu, ps, 8);
    float s2 = __shfl_sync(0xffffffffu, ps, 16);
    float s3 = __shfl_sync(0xffffffffu, ps, 24);
    float d0 = __shfl_sync(0xffffffffu, pd, 0);
    float d1 = __shfl_sync(0xffffffffu, pd, 8);
    float d2 = __shfl_sync(0xffffffffu, pd, 16);
    float d3 = __shfl_sync(0xffffffffu, pd, 24);
    if (lane == 0) {
        g_ssrc[gw] = make_float4(s0, s1, s2, s3);
        g_sdst[gw] = make_float4(d0, d1, d2, d3);
    }
}

// ---------------- CSR construction ----------------
__global__ void hist_kernel(const int2* __restrict__ adj, int E) {
    int e = blockIdx.x * blockDim.x + threadIdx.x;
    if (e < E) atomicAdd(&g_deg[adj[e].y], 1);
}

// parallel exclusive scan of g_deg -> g_off (3 kernels)
__global__ void scan1_kernel(int Nn) {
    __shared__ int ws[16];
    int tid = threadIdx.x, lane = tid & 31, wid = tid >> 5;
    int i = blockIdx.x * 512 + tid;
    int d = (i < Nn) ? g_deg[i] : 0;
    int v = d;
#pragma unroll
    for (int o = 1; o < 32; o <<= 1) {
        int t = __shfl_up_sync(0xffffffffu, v, o);
        if (lane >= o) v += t;
    }
    if (lane == 31) ws[wid] = v;
    __syncthreads();
    if (tid == 0) {
        int run = 0;
#pragma unroll
        for (int k = 0; k < 16; ++k) { int t = ws[k]; ws[k] = run; run += t; }
        g_bsum[blockIdx.x] = run;
    }
    __syncthreads();
    int excl = v - d + ws[wid];
    if (i < Nn) g_off[i] = excl;
}

__global__ void scan2_kernel(int NB, int Nn, int E) {
    __shared__ int ws[4];
    int tid = threadIdx.x, lane = tid & 31, wid = tid >> 5;
    int d = (tid < NB) ? g_bsum[tid] : 0;
    int v = d;
#pragma unroll
    for (int o = 1; o < 32; o <<= 1) {
        int t = __shfl_up_sync(0xffffffffu, v, o);
        if (lane >= o) v += t;
    }
    if (lane == 31) ws[wid] = v;
    __syncthreads();
    if (tid == 0) {
        int run = 0;
#pragma unroll
        for (int k = 0; k < 4; ++k) { int t = ws[k]; ws[k] = run; run += t; }
    }
    __syncthreads();
    int excl = v - d + ws[wid];
    if (tid < NB) g_bsum[tid] = excl;
    if (tid == 0) g_off[Nn] = E;
}

__global__ void scan3_kernel(int Nn) {
    int i = blockIdx.x * 512 + threadIdx.x;
    if (i < Nn) {
        int o = g_off[i] + g_bsum[blockIdx.x];
        g_off[i] = o;
        g_cur[i] = o;
    }
}

// scatter: build CSR and store p = gate*exp(tanh(ss+sd)) per head
__global__ void scatter_kernel(const int2* __restrict__ adj,
                               const float* __restrict__ w, int E) {
    int e = blockIdx.x * blockDim.x + threadIdx.x;
    if (e >= E) return;
    int2 a   = adj[e];
    int  pos = atomicAdd(&g_cur[a.y], 1);
    float g  = fmaxf(w[e], EPSW);
    float4 ss = g_ssrc[a.x];
    float4 sd = g_sdst[a.y];
    float4 p;
    p.x = g * __expf(tanhf(ss.x + sd.x));
    p.y = g * __expf(tanhf(ss.y + sd.y));
    p.z = g * __expf(tanhf(ss.z + sd.z));
    p.w = g * __expf(tanhf(ss.w + sd.w));
    g_epk[pos] = make_int2(a.x, __float_as_int(g));
    g_ep[pos]  = p;
}

// ------- aggregation: SINGLE fused pass (normalize once at the end) -------
__device__ __forceinline__ float gelu_exact(float v) {
    return 0.5f * v * (1.0f + erff(v * 0.70710678118654752f));
}

__global__ void aggregate_kernel(float* __restrict__ out, int Nn) {
    int n    = (blockIdx.x * blockDim.x + threadIdx.x) >> 5;
    int lane = threadIdx.x & 31;
    if (n >= Nn) return;

    const int start = g_off[n];
    const int end   = g_off[n + 1];

    // lane covers output dims lane*4..+3; head = lane>>3.
    // out = (sum_e p_e*g_e*h_e) / (sum_e p_e)  — denom accumulated in-loop.
    const int hh = lane >> 3;
    float den = 0.f;
    float4 acc = make_float4(0.f, 0.f, 0.f, 0.f);
    const float* ep_f = (const float*)g_ep;
#pragma unroll 2
    for (int e = start; e < end; ++e) {
        int2  ek  = g_epk[e];
        float g   = __int_as_float(ek.y);
        float pv  = ep_f[(size_t)e * 4 + hh];
        den += pv;
        float wgt = pv * g;
        float4 hv = g_h4[(size_t)ek.x * 32 + lane];
        acc.x = fmaf(wgt, hv.x, acc.x);
        acc.y = fmaf(wgt, hv.y, acc.y);
        acc.z = fmaf(wgt, hv.z, acc.z);
        acc.w = fmaf(wgt, hv.w, acc.w);
    }

    float inv = (end > start) ? (1.0f / den) : 0.f;
    float4 res;
    res.x = gelu_exact(acc.x * inv);
    res.y = gelu_exact(acc.y * inv);
    res.z = gelu_exact(acc.z * inv);
    res.w = gelu_exact(acc.w * inv);
    *(float4*)&out[(size_t)n * HD + lane * 4] = res;
}

// ---------------- launch ----------------
extern "C" void kernel_launch(void* const* d_in, const int* in_sizes, int n_in,
                              void* d_out, int out_size) {
    const float* x     = (const float*)d_in[0];
    const int*   adj   = (const int*)d_in[1];
    const float* w     = (const float*)d_in[2];
    const float* Wm    = (const float*)d_in[3];
    const float* a_src = (const float*)d_in[4];
    const float* a_dst = (const float*)d_in[5];
    float*       out   = (float*)d_out;

    const int Nn   = in_sizes[0] / DIN;
    const int E    = in_sizes[2];
    const int Npad = ((Nn + 127) / 128) * 128;
    const int NB   = (Nn + 511) / 512;
    const int prepN = (HD * DIN > Nn + 1) ? HD * DIN : Nn + 1;

    cudaFuncSetAttribute(hmma_gemm_kernel,
                         cudaFuncAttributeMaxDynamicSharedMemorySize, SM_TOT);

    prep_kernel<<<(prepN + 255) / 256, 256>>>(Wm, Nn);
    hmma_gemm_kernel<<<Npad / 128, 256, SM_TOT>>>(x, Nn);
    sdot_kernel<<<(Nn * 32 + 255) / 256, 256>>>((const float4*)a_src,
                                                (const float4*)a_dst, Nn);
    hist_kernel<<<(E + 255) / 256, 256>>>((const int2*)adj, E);
    scan1_kernel<<<NB, 512>>>(Nn);
    scan2_kernel<<<1, 128>>>(NB, Nn, E);
    scan3_kernel<<<NB, 512>>>(Nn);
    scatter_kernel<<<(E + 255) / 256, 256>>>((const int2*)adj, w, E);
    aggregate_kernel<<<(Nn * 32 + 255) / 256, 256>>>(out, Nn);
}

// round 13
// speedup vs baseline: 1.5458x; 1.0432x over previous
#include <cuda_runtime.h>
#include <cuda_bf16.h>
#include <math.h>
#include <cstdint>

#define MAXN 50000
#define NPAD 50048
#define MAXE 800000
#define DIN  256
#define HD   128
#define EPSW 1e-6f

// ---------------- scratch ----------------
__device__ __align__(16) float4 g_h4[NPAD * 32];          // h: [N][128]
__device__ float4 g_ssrc[MAXN];
__device__ float4 g_sdst[MAXN];
__device__ int    g_deg[MAXN + 1];
__device__ int    g_off[MAXN + 1];
__device__ int    g_cur[MAXN + 1];
__device__ int    g_bsum[128];
__device__ __align__(16) int2   g_epk[MAXE];              // (src, gate bits)
__device__ __align__(16) float4 g_ep[MAXE];               // p = gate*exp(tanh) per head
__device__ __align__(16) __nv_bfloat16 g_wthi[HD * DIN];  // W^T hi: [n][k]
__device__ __align__(16) __nv_bfloat16 g_wtlo[HD * DIN];  // W^T lo: [n][k]

__device__ __forceinline__ uint32_t smem_u32(const void* p) {
    uint32_t a;
    asm("{ .reg .u64 t; cvta.to.shared.u64 t, %1; cvt.u32.u64 %0, t; }" : "=r"(a) : "l"(p));
    return a;
}
__device__ __forceinline__ void mma16816(float* d, const uint32_t* a,
                                         uint32_t b0, uint32_t b1) {
    asm volatile(
        "mma.sync.aligned.m16n8k16.row.col.f32.bf16.bf16.f32 "
        "{%0,%1,%2,%3}, {%4,%5,%6,%7}, {%8,%9}, {%0,%1,%2,%3};"
        : "+f"(d[0]), "+f"(d[1]), "+f"(d[2]), "+f"(d[3])
        : "r"(a[0]), "r"(a[1]), "r"(a[2]), "r"(a[3]), "r"(b0), "r"(b1));
}
__device__ __forceinline__ void ldmat_x4(uint32_t* f, uint32_t addr) {
    asm volatile("ldmatrix.sync.aligned.m8n8.x4.shared.b16 {%0,%1,%2,%3}, [%4];"
                 : "=r"(f[0]), "=r"(f[1]), "=r"(f[2]), "=r"(f[3]) : "r"(addr));
}

// ============ prep: W^T bf16 hi/lo + zero degree counters ============
__global__ void prep_kernel(const float* __restrict__ Wm, int Nn) {
    int i = blockIdx.x * blockDim.x + threadIdx.x;
    if (i < HD * DIN) {
        int n = i >> 8;
        int k = i & 255;
        float v = Wm[k * HD + n];
        __nv_bfloat16 hi = __float2bfloat16(v);
        float lo = v - __bfloat162float(hi);
        g_wthi[i] = hi;
        g_wtlo[i] = __float2bfloat16(lo);
    }
    if (i <= Nn) g_deg[i] = 0;
}

// =============== HMMA GEMM: h = x @ W (3-product bf16 split) ================
// 2 CTAs/SM: one CTA's load/convert phase overlaps the other's MMA phase.
#define APITCH 72
#define TILE_B (128 * APITCH * 2)
#define SM_AH  0
#define SM_AL  (SM_AH + TILE_B)
#define SM_BH  (SM_AL + TILE_B)
#define SM_BL  (SM_BH + TILE_B)
#define SM_TOT (SM_BL + TILE_B)

__global__ void __launch_bounds__(256, 2) hmma_gemm_kernel(const float* __restrict__ x,
                                                           int Nn) {
    extern __shared__ char smem[];
    const uint32_t sb = smem_u32(smem);
    const int tid  = threadIdx.x;
    const int wid  = tid >> 5;
    const int lane = tid & 31;
    const int wm   = wid & 3;
    const int wn   = wid >> 2;
    const int rowBase = blockIdx.x * 128;

    float acc[2][8][4];
#pragma unroll
    for (int mt = 0; mt < 2; ++mt)
#pragma unroll
        for (int nt = 0; nt < 8; ++nt)
#pragma unroll
            for (int q = 0; q < 4; ++q) acc[mt][nt][q] = 0.f;

    for (int c = 0; c < 4; ++c) {
        const int k0 = c * 64;
#pragma unroll
        for (int j = 0; j < 8; ++j) {
            int idx = j * 256 + tid;
            int r   = idx >> 4;
            int c4  = idx & 15;
            int grow = rowBase + r;
            float4 v = make_float4(0.f, 0.f, 0.f, 0.f);
            if (grow < Nn)
                v = *(const float4*)&x[(size_t)grow * DIN + k0 + c4 * 4];
            float f[4] = {v.x, v.y, v.z, v.w};
            __nv_bfloat16 hi[4], lo[4];
#pragma unroll
            for (int q = 0; q < 4; ++q) {
                hi[q] = __float2bfloat16(f[q]);
                lo[q] = __float2bfloat16(f[q] - __bfloat162float(hi[q]));
            }
            __nv_bfloat162 h0 = __halves2bfloat162(hi[0], hi[1]);
            __nv_bfloat162 h1 = __halves2bfloat162(hi[2], hi[3]);
            __nv_bfloat162 l0 = __halves2bfloat162(lo[0], lo[1]);
            __nv_bfloat162 l1 = __halves2bfloat162(lo[2], lo[3]);
            uint2 uh, ul;
            uh.x = *reinterpret_cast<uint32_t*>(&h0);
            uh.y = *reinterpret_cast<uint32_t*>(&h1);
            ul.x = *reinterpret_cast<uint32_t*>(&l0);
            ul.y = *reinterpret_cast<uint32_t*>(&l1);
            int off = r * (APITCH * 2) + c4 * 8;
            *(uint2*)(smem + SM_AH + off) = uh;
            *(uint2*)(smem + SM_AL + off) = ul;
        }
#pragma unroll
        for (int j = 0; j < 4; ++j) {
            int idx = j * 256 + tid;
            int r   = idx >> 3;
            int c16 = idx & 7;
            size_t gsrc = (size_t)r * DIN + k0 + c16 * 8;
            uint4 vh = *(const uint4*)&g_wthi[gsrc];
            uint4 vl = *(const uint4*)&g_wtlo[gsrc];
            int off = r * (APITCH * 2) + c16 * 16;
            *(uint4*)(smem + SM_BH + off) = vh;
            *(uint4*)(smem + SM_BL + off) = vl;
        }
        __syncthreads();

        const __nv_bfloat16* BsH = (const __nv_bfloat16*)(smem + SM_BH);
        const __nv_bfloat16* BsL = (const __nv_bfloat16*)(smem + SM_BL);
#pragma unroll
        for (int kk = 0; kk < 4; ++kk) {
            const int kbase = kk * 16;
            uint32_t ah[2][4], al[2][4];
            const int lr = lane & 15;
            const int lc = (lane >> 4) * 8;
#pragma unroll
            for (int mt = 0; mt < 2; ++mt) {
                int m = wm * 32 + mt * 16 + lr;
                uint32_t byteoff = (uint32_t)(m * (APITCH * 2) + (kbase + lc) * 2);
                ldmat_x4(ah[mt], sb + SM_AH + byteoff);
                ldmat_x4(al[mt], sb + SM_AL + byteoff);
            }
            const int bn = (lane >> 2);
            const int bk = kbase + (lane & 3) * 2;
#pragma unroll
            for (int nt = 0; nt < 8; ++nt) {
                int n = wn * 64 + nt * 8 + bn;
                uint32_t bh0 = *(const uint32_t*)&BsH[n * APITCH + bk];
                uint32_t bh1 = *(const uint32_t*)&BsH[n * APITCH + bk + 8];
                uint32_t bl0 = *(const uint32_t*)&BsL[n * APITCH + bk];
                uint32_t bl1 = *(const uint32_t*)&BsL[n * APITCH + bk + 8];
#pragma unroll
                for (int mt = 0; mt < 2; ++mt) {
                    mma16816(acc[mt][nt], ah[mt], bh0, bh1);
                    mma16816(acc[mt][nt], ah[mt], bl0, bl1);
                    mma16816(acc[mt][nt], al[mt], bh0, bh1);
                }
            }
        }
        __syncthreads();
    }

    float* gh = (float*)g_h4;
    const int er = lane >> 2;
    const int ec = (lane & 3) * 2;
#pragma unroll
    for (int mt = 0; mt < 2; ++mt) {
        int r1 = rowBase + wm * 32 + mt * 16 + er;
        int r2 = r1 + 8;
#pragma unroll
        for (int nt = 0; nt < 8; ++nt) {
            int cc = wn * 64 + nt * 8 + ec;
            if (r1 < Nn)
                *(float2*)&gh[(size_t)r1 * HD + cc] =
                    make_float2(acc[mt][nt][0], acc[mt][nt][1]);
            if (r2 < Nn)
                *(float2*)&gh[(size_t)r2 * HD + cc] =
                    make_float2(acc[mt][nt][2], acc[mt][nt][3]);
        }
    }
}

// -------- per-node attention scalars (float4 loads, 8-lane reduce) --------
__global__ void sdot_kernel(const float4* __restrict__ a_src4,
                            const float4* __restrict__ a_dst4,
                            int Nn) {
    int gw   = (blockIdx.x * blockDim.x + threadIdx.x) >> 5;
    int lane = threadIdx.x & 31;
    if (gw >= Nn) return;

    float4 hv = g_h4[(size_t)gw * 32 + lane];
    float4 as = a_src4[lane];
    float4 ad = a_dst4[lane];
    float ps = hv.x * as.x + hv.y * as.y + hv.z * as.z + hv.w * as.w;
    float pd = hv.x * ad.x + hv.y * ad.y + hv.z * ad.z + hv.w * ad.w;
#pragma unroll
    for (int o = 1; o < 8; o <<= 1) {
        ps += __shfl_xor_sync(0xffffffffu, ps, o);
        pd += __shfl_xor_sync(0xffffffffu, pd, o);
    }
    float s0 = __shfl_sync(0xffffffffu, ps, 0);
    float s1 = __shfl_sync(0xffffffffu, ps, 8);
    float s2 = __shfl_sync(0xffffffffu, ps, 16);
    float s3 = __shfl_sync(0xffffffffu, ps, 24);
    float d0 = __shfl_sync(0xffffffffu, pd, 0);
    float d1 = __shfl_sync(0xffffffffu, pd, 8);
    float d2 = __shfl_sync(0xffffffffu, pd, 16);
    float d3 = __shfl_sync(0xffffffffu, pd, 24);
    if (lane == 0) {
        g_ssrc[gw] = make_float4(s0, s1, s2, s3);
        g_sdst[gw] = make_float4(d0, d1, d2, d3);
    }
}

// ---------------- CSR construction ----------------
__global__ void hist_kernel(const int2* __restrict__ adj, int E) {
    int e = blockIdx.x * blockDim.x + threadIdx.x;
    if (e < E) atomicAdd(&g_deg[adj[e].y], 1);
}

// parallel exclusive scan of g_deg -> g_off (3 kernels)
__global__ void scan1_kernel(int Nn) {
    __shared__ int ws[16];
    int tid = threadIdx.x, lane = tid & 31, wid = tid >> 5;
    int i = blockIdx.x * 512 + tid;
    int d = (i < Nn) ? g_deg[i] : 0;
    int v = d;
#pragma unroll
    for (int o = 1; o < 32; o <<= 1) {
        int t = __shfl_up_sync(0xffffffffu, v, o);
        if (lane >= o) v += t;
    }
    if (lane == 31) ws[wid] = v;
    __syncthreads();
    if (tid == 0) {
        int run = 0;
#pragma unroll
        for (int k = 0; k < 16; ++k) { int t = ws[k]; ws[k] = run; run += t; }
        g_bsum[blockIdx.x] = run;
    }
    __syncthreads();
    int excl = v - d + ws[wid];
    if (i < Nn) g_off[i] = excl;
}

__global__ void scan2_kernel(int NB, int Nn, int E) {
    __shared__ int ws[4];
    int tid = threadIdx.x, lane = tid & 31, wid = tid >> 5;
    int d = (tid < NB) ? g_bsum[tid] : 0;
    int v = d;
#pragma unroll
    for (int o = 1; o < 32; o <<= 1) {
        int t = __shfl_up_sync(0xffffffffu, v, o);
        if (lane >= o) v += t;
    }
    if (lane == 31) ws[wid] = v;
    __syncthreads();
    if (tid == 0) {
        int run = 0;
#pragma unroll
        for (int k = 0; k < 4; ++k) { int t = ws[k]; ws[k] = run; run += t; }
    }
    __syncthreads();
    int excl = v - d + ws[wid];
    if (tid < NB) g_bsum[tid] = excl;
    if (tid == 0) g_off[Nn] = E;
}

__global__ void scan3_kernel(int Nn) {
    int i = blockIdx.x * 512 + threadIdx.x;
    if (i < Nn) {
        int o = g_off[i] + g_bsum[blockIdx.x];
        g_off[i] = o;
        g_cur[i] = o;
    }
}

// scatter: build CSR and store p = gate*exp(tanh(ss+sd)) per head
__global__ void scatter_kernel(const int2* __restrict__ adj,
                               const float* __restrict__ w, int E) {
    int e = blockIdx.x * blockDim.x + threadIdx.x;
    if (e >= E) return;
    int2 a   = adj[e];
    int  pos = atomicAdd(&g_cur[a.y], 1);
    float g  = fmaxf(w[e], EPSW);
    float4 ss = g_ssrc[a.x];
    float4 sd = g_sdst[a.y];
    float4 p;
    p.x = g * __expf(tanhf(ss.x + sd.x));
    p.y = g * __expf(tanhf(ss.y + sd.y));
    p.z = g * __expf(tanhf(ss.z + sd.z));
    p.w = g * __expf(tanhf(ss.w + sd.w));
    g_epk[pos] = make_int2(a.x, __float_as_int(g));
    g_ep[pos]  = p;
}

// ------- aggregation: SINGLE fused pass (normalize once at the end) -------
__device__ __forceinline__ float gelu_exact(float v) {
    return 0.5f * v * (1.0f + erff(v * 0.70710678118654752f));
}

__global__ void aggregate_kernel(float* __restrict__ out, int Nn) {
    int n    = (blockIdx.x * blockDim.x + threadIdx.x) >> 5;
    int lane = threadIdx.x & 31;
    if (n >= Nn) return;

    const int start = g_off[n];
    const int end   = g_off[n + 1];

    const int hh = lane >> 3;
    float den = 0.f;
    float4 acc = make_float4(0.f, 0.f, 0.f, 0.f);
    const float* ep_f = (const float*)g_ep;
#pragma unroll 2
    for (int e = start; e < end; ++e) {
        int2  ek  = g_epk[e];
        float g   = __int_as_float(ek.y);
        float pv  = ep_f[(size_t)e * 4 + hh];
        den += pv;
        float wgt = pv * g;
        float4 hv = g_h4[(size_t)ek.x * 32 + lane];
        acc.x = fmaf(wgt, hv.x, acc.x);
        acc.y = fmaf(wgt, hv.y, acc.y);
        acc.z = fmaf(wgt, hv.z, acc.z);
        acc.w = fmaf(wgt, hv.w, acc.w);
    }

    float inv = (end > start) ? (1.0f / den) : 0.f;
    float4 res;
    res.x = gelu_exact(acc.x * inv);
    res.y = gelu_exact(acc.y * inv);
    res.z = gelu_exact(acc.z * inv);
    res.w = gelu_exact(acc.w * inv);
    *(float4*)&out[(size_t)n * HD + lane * 4] = res;
}

// ---------------- launch ----------------
extern "C" void kernel_launch(void* const* d_in, const int* in_sizes, int n_in,
                              void* d_out, int out_size) {
    const float* x     = (const float*)d_in[0];
    const int*   adj   = (const int*)d_in[1];
    const float* w     = (const float*)d_in[2];
    const float* Wm    = (const float*)d_in[3];
    const float* a_src = (const float*)d_in[4];
    const float* a_dst = (const float*)d_in[5];
    float*       out   = (float*)d_out;

    const int Nn   = in_sizes[0] / DIN;
    const int E    = in_sizes[2];
    const int Npad = ((Nn + 127) / 128) * 128;
    const int NB   = (Nn + 511) / 512;
    const int prepN = (HD * DIN > Nn + 1) ? HD * DIN : Nn + 1;

    cudaFuncSetAttribute(hmma_gemm_kernel,
                         cudaFuncAttributeMaxDynamicSharedMemorySize, SM_TOT);

    prep_kernel<<<(prepN + 255) / 256, 256>>>(Wm, Nn);
    hmma_gemm_kernel<<<Npad / 128, 256, SM_TOT>>>(x, Nn);
    sdot_kernel<<<(Nn * 32 + 255) / 256, 256>>>((const float4*)a_src,
                                                (const float4*)a_dst, Nn);
    hist_kernel<<<(E + 255) / 256, 256>>>((const int2*)adj, E);
    scan1_kernel<<<NB, 512>>>(Nn);
    scan2_kernel<<<1, 128>>>(NB, Nn, E);
    scan3_kernel<<<NB, 512>>>(Nn);
    scatter_kernel<<<(E + 255) / 256, 256>>>((const int2*)adj, w, E);
    aggregate_kernel<<<(Nn * 32 + 255) / 256, 256>>>(out, Nn);
}

// round 15
// speedup vs baseline: 1.5844x; 1.0250x over previous
#include <cuda_runtime.h>
#include <cuda_bf16.h>
#include <math.h>
#include <cstdint>

#define MAXN 50000
#define NPAD 50048
#define MAXE 800000
#define DIN  256
#define HD   128
#define EPSW 1e-6f

// ---------------- scratch ----------------
__device__ __align__(16) float4 g_h4[NPAD * 32];          // h: [N][128]
__device__ float4 g_ssrc[MAXN];
__device__ float4 g_sdst[MAXN];
__device__ int    g_deg[MAXN + 1];
__device__ int    g_off[MAXN + 1];
__device__ int    g_cur[MAXN + 1];
__device__ int    g_bsum[128];
__device__ __align__(16) int2   g_epk[MAXE];              // (src, gate bits)
__device__ __align__(16) float4 g_ep[MAXE];               // p = gate*exp(tanh) per head
__device__ __align__(16) __nv_bfloat16 g_wthi[HD * DIN];  // W^T hi: [n][k]
__device__ __align__(16) __nv_bfloat16 g_wtlo[HD * DIN];  // W^T lo: [n][k]

__device__ __forceinline__ uint32_t smem_u32(const void* p) {
    uint32_t a;
    asm("{ .reg .u64 t; cvta.to.shared.u64 t, %1; cvt.u32.u64 %0, t; }" : "=r"(a) : "l"(p));
    return a;
}
__device__ __forceinline__ void mma16816(float* d, const uint32_t* a,
                                         uint32_t b0, uint32_t b1) {
    asm volatile(
        "mma.sync.aligned.m16n8k16.row.col.f32.bf16.bf16.f32 "
        "{%0,%1,%2,%3}, {%4,%5,%6,%7}, {%8,%9}, {%0,%1,%2,%3};"
        : "+f"(d[0]), "+f"(d[1]), "+f"(d[2]), "+f"(d[3])
        : "r"(a[0]), "r"(a[1]), "r"(a[2]), "r"(a[3]), "r"(b0), "r"(b1));
}
__device__ __forceinline__ void ldmat_x4(uint32_t* f, uint32_t addr) {
    asm volatile("ldmatrix.sync.aligned.m8n8.x4.shared.b16 {%0,%1,%2,%3}, [%4];"
                 : "=r"(f[0]), "=r"(f[1]), "=r"(f[2]), "=r"(f[3]) : "r"(addr));
}

// ============ prep: W^T bf16 hi/lo + zero degree counters ============
__global__ void prep_kernel(const float* __restrict__ Wm, int Nn) {
    int i = blockIdx.x * blockDim.x + threadIdx.x;
    if (i < HD * DIN) {
        int n = i >> 8;
        int k = i & 255;
        float v = Wm[k * HD + n];
        __nv_bfloat16 hi = __float2bfloat16(v);
        float lo = v - __bfloat162float(hi);
        g_wthi[i] = hi;
        g_wtlo[i] = __float2bfloat16(lo);
    }
}

// zero degree counters (runs on the CSR branch)
__global__ void zdeg_kernel(int Nn) {
    int i = blockIdx.x * blockDim.x + threadIdx.x;
    if (i <= Nn) g_deg[i] = 0;
}

// =============== HMMA GEMM: h = x @ W (3-product bf16 split) ================
#define APITCH 72
#define TILE_B (128 * APITCH * 2)
#define SM_AH  0
#define SM_AL  (SM_AH + TILE_B)
#define SM_BH  (SM_AL + TILE_B)
#define SM_BL  (SM_BH + TILE_B)
#define SM_TOT (SM_BL + TILE_B)

__global__ void __launch_bounds__(256, 2) hmma_gemm_kernel(const float* __restrict__ x,
                                                           int Nn) {
    extern __shared__ char smem[];
    const uint32_t sb = smem_u32(smem);
    const int tid  = threadIdx.x;
    const int wid  = tid >> 5;
    const int lane = tid & 31;
    const int wm   = wid & 3;
    const int wn   = wid >> 2;
    const int rowBase = blockIdx.x * 128;

    float acc[2][8][4];
#pragma unroll
    for (int mt = 0; mt < 2; ++mt)
#pragma unroll
        for (int nt = 0; nt < 8; ++nt)
#pragma unroll
            for (int q = 0; q < 4; ++q) acc[mt][nt][q] = 0.f;

    for (int c = 0; c < 4; ++c) {
        const int k0 = c * 64;
#pragma unroll
        for (int j = 0; j < 8; ++j) {
            int idx = j * 256 + tid;
            int r   = idx >> 4;
            int c4  = idx & 15;
            int grow = rowBase + r;
            float4 v = make_float4(0.f, 0.f, 0.f, 0.f);
            if (grow < Nn)
                v = *(const float4*)&x[(size_t)grow * DIN + k0 + c4 * 4];
            float f[4] = {v.x, v.y, v.z, v.w};
            __nv_bfloat16 hi[4], lo[4];
#pragma unroll
            for (int q = 0; q < 4; ++q) {
                hi[q] = __float2bfloat16(f[q]);
                lo[q] = __float2bfloat16(f[q] - __bfloat162float(hi[q]));
            }
            __nv_bfloat162 h0 = __halves2bfloat162(hi[0], hi[1]);
            __nv_bfloat162 h1 = __halves2bfloat162(hi[2], hi[3]);
            __nv_bfloat162 l0 = __halves2bfloat162(lo[0], lo[1]);
            __nv_bfloat162 l1 = __halves2bfloat162(lo[2], lo[3]);
            uint2 uh, ul;
            uh.x = *reinterpret_cast<uint32_t*>(&h0);
            uh.y = *reinterpret_cast<uint32_t*>(&h1);
            ul.x = *reinterpret_cast<uint32_t*>(&l0);
            ul.y = *reinterpret_cast<uint32_t*>(&l1);
            int off = r * (APITCH * 2) + c4 * 8;
            *(uint2*)(smem + SM_AH + off) = uh;
            *(uint2*)(smem + SM_AL + off) = ul;
        }
#pragma unroll
        for (int j = 0; j < 4; ++j) {
            int idx = j * 256 + tid;
            int r   = idx >> 3;
            int c16 = idx & 7;
            size_t gsrc = (size_t)r * DIN + k0 + c16 * 8;
            uint4 vh = *(const uint4*)&g_wthi[gsrc];
            uint4 vl = *(const uint4*)&g_wtlo[gsrc];
            int off = r * (APITCH * 2) + c16 * 16;
            *(uint4*)(smem + SM_BH + off) = vh;
            *(uint4*)(smem + SM_BL + off) = vl;
        }
        __syncthreads();

        const __nv_bfloat16* BsH = (const __nv_bfloat16*)(smem + SM_BH);
        const __nv_bfloat16* BsL = (const __nv_bfloat16*)(smem + SM_BL);
#pragma unroll
        for (int kk = 0; kk < 4; ++kk) {
            const int kbase = kk * 16;
            uint32_t ah[2][4], al[2][4];
            const int lr = lane & 15;
            const int lc = (lane >> 4) * 8;
#pragma unroll
            for (int mt = 0; mt < 2; ++mt) {
                int m = wm * 32 + mt * 16 + lr;
                uint32_t byteoff = (uint32_t)(m * (APITCH * 2) + (kbase + lc) * 2);
                ldmat_x4(ah[mt], sb + SM_AH + byteoff);
                ldmat_x4(al[mt], sb + SM_AL + byteoff);
            }
            const int bn = (lane >> 2);
            const int bk = kbase + (lane & 3) * 2;
#pragma unroll
            for (int nt = 0; nt < 8; ++nt) {
                int n = wn * 64 + nt * 8 + bn;
                uint32_t bh0 = *(const uint32_t*)&BsH[n * APITCH + bk];
                uint32_t bh1 = *(const uint32_t*)&BsH[n * APITCH + bk + 8];
                uint32_t bl0 = *(const uint32_t*)&BsL[n * APITCH + bk];
                uint32_t bl1 = *(const uint32_t*)&BsL[n * APITCH + bk + 8];
#pragma unroll
                for (int mt = 0; mt < 2; ++mt) {
                    mma16816(acc[mt][nt], ah[mt], bh0, bh1);
                    mma16816(acc[mt][nt], ah[mt], bl0, bl1);
                    mma16816(acc[mt][nt], al[mt], bh0, bh1);
                }
            }
        }
        __syncthreads();
    }

    float* gh = (float*)g_h4;
    const int er = lane >> 2;
    const int ec = (lane & 3) * 2;
#pragma unroll
    for (int mt = 0; mt < 2; ++mt) {
        int r1 = rowBase + wm * 32 + mt * 16 + er;
        int r2 = r1 + 8;
#pragma unroll
        for (int nt = 0; nt < 8; ++nt) {
            int cc = wn * 64 + nt * 8 + ec;
            if (r1 < Nn)
                *(float2*)&gh[(size_t)r1 * HD + cc] =
                    make_float2(acc[mt][nt][0], acc[mt][nt][1]);
            if (r2 < Nn)
                *(float2*)&gh[(size_t)r2 * HD + cc] =
                    make_float2(acc[mt][nt][2], acc[mt][nt][3]);
        }
    }
}

// -------- per-node attention scalars (float4 loads, 8-lane reduce) --------
__global__ void sdot_kernel(const float4* __restrict__ a_src4,
                            const float4* __restrict__ a_dst4,
                            int Nn) {
    int gw   = (blockIdx.x * blockDim.x + threadIdx.x) >> 5;
    int lane = threadIdx.x & 31;
    if (gw >= Nn) return;

    float4 hv = g_h4[(size_t)gw * 32 + lane];
    float4 as = a_src4[lane];
    float4 ad = a_dst4[lane];
    float ps = hv.x * as.x + hv.y * as.y + hv.z * as.z + hv.w * as.w;
    float pd = hv.x * ad.x + hv.y * ad.y + hv.z * ad.z + hv.w * ad.w;
#pragma unroll
    for (int o = 1; o < 8; o <<= 1) {
        ps += __shfl_xor_sync(0xffffffffu, ps, o);
        pd += __shfl_xor_sync(0xffffffffu, pd, o);
    }
    float s0 = __shfl_sync(0xffffffffu, ps, 0);
    float s1 = __shfl_sync(0xffffffffu, ps, 8);
    float s2 = __shfl_sync(0xffffffffu, ps, 16);
    float s3 = __shfl_sync(0xffffffffu, ps, 24);
    float d0 = __shfl_sync(0xffffffffu, pd, 0);
    float d1 = __shfl_sync(0xffffffffu, pd, 8);
    float d2 = __shfl_sync(0xffffffffu, pd, 16);
    float d3 = __shfl_sync(0xffffffffu, pd, 24);
    if (lane == 0) {
        g_ssrc[gw] = make_float4(s0, s1, s2, s3);
        g_sdst[gw] = make_float4(d0, d1, d2, d3);
    }
}

// ---------------- CSR construction ----------------
__global__ void hist_kernel(const int2* __restrict__ adj, int E) {
    int e = blockIdx.x * blockDim.x + threadIdx.x;
    if (e < E) atomicAdd(&g_deg[adj[e].y], 1);
}

__global__ void scan1_kernel(int Nn) {
    __shared__ int ws[16];
    int tid = threadIdx.x, lane = tid & 31, wid = tid >> 5;
    int i = blockIdx.x * 512 + tid;
    int d = (i < Nn) ? g_deg[i] : 0;
    int v = d;
#pragma unroll
    for (int o = 1; o < 32; o <<= 1) {
        int t = __shfl_up_sync(0xffffffffu, v, o);
        if (lane >= o) v += t;
    }
    if (lane == 31) ws[wid] = v;
    __syncthreads();
    if (tid == 0) {
        int run = 0;
#pragma unroll
        for (int k = 0; k < 16; ++k) { int t = ws[k]; ws[k] = run; run += t; }
        g_bsum[blockIdx.x] = run;
    }
    __syncthreads();
    int excl = v - d + ws[wid];
    if (i < Nn) g_off[i] = excl;
}

__global__ void scan2_kernel(int NB, int Nn, int E) {
    __shared__ int ws[4];
    int tid = threadIdx.x, lane = tid & 31, wid = tid >> 5;
    int d = (tid < NB) ? g_bsum[tid] : 0;
    int v = d;
#pragma unroll
    for (int o = 1; o < 32; o <<= 1) {
        int t = __shfl_up_sync(0xffffffffu, v, o);
        if (lane >= o) v += t;
    }
    if (lane == 31) ws[wid] = v;
    __syncthreads();
    if (tid == 0) {
        int run = 0;
#pragma unroll
        for (int k = 0; k < 4; ++k) { int t = ws[k]; ws[k] = run; run += t; }
    }
    __syncthreads();
    int excl = v - d + ws[wid];
    if (tid < NB) g_bsum[tid] = excl;
    if (tid == 0) g_off[Nn] = E;
}

__global__ void scan3_kernel(int Nn) {
    int i = blockIdx.x * 512 + threadIdx.x;
    if (i < Nn) {
        int o = g_off[i] + g_bsum[blockIdx.x];
        g_off[i] = o;
        g_cur[i] = o;
    }
}

// scatter: build CSR and store p = gate*exp(tanh(ss+sd)) per head
__global__ void scatter_kernel(const int2* __restrict__ adj,
                               const float* __restrict__ w, int E) {
    int e = blockIdx.x * blockDim.x + threadIdx.x;
    if (e >= E) return;
    int2 a   = adj[e];
    int  pos = atomicAdd(&g_cur[a.y], 1);
    float g  = fmaxf(w[e], EPSW);
    float4 ss = g_ssrc[a.x];
    float4 sd = g_sdst[a.y];
    float4 p;
    p.x = g * __expf(tanhf(ss.x + sd.x));
    p.y = g * __expf(tanhf(ss.y + sd.y));
    p.z = g * __expf(tanhf(ss.z + sd.z));
    p.w = g * __expf(tanhf(ss.w + sd.w));
    g_epk[pos] = make_int2(a.x, __float_as_int(g));
    g_ep[pos]  = p;
}

// ------- aggregation: SINGLE fused pass (normalize once at the end) -------
__device__ __forceinline__ float gelu_exact(float v) {
    return 0.5f * v * (1.0f + erff(v * 0.70710678118654752f));
}

__global__ void aggregate_kernel(float* __restrict__ out, int Nn) {
    int n    = (blockIdx.x * blockDim.x + threadIdx.x) >> 5;
    int lane = threadIdx.x & 31;
    if (n >= Nn) return;

    const int start = g_off[n];
    const int end   = g_off[n + 1];

    const int hh = lane >> 3;
    float den = 0.f;
    float4 acc = make_float4(0.f, 0.f, 0.f, 0.f);
    const float* ep_f = (const float*)g_ep;
#pragma unroll 2
    for (int e = start; e < end; ++e) {
        int2  ek  = g_epk[e];
        float g   = __int_as_float(ek.y);
        float pv  = ep_f[(size_t)e * 4 + hh];
        den += pv;
        float wgt = pv * g;
        float4 hv = g_h4[(size_t)ek.x * 32 + lane];
        acc.x = fmaf(wgt, hv.x, acc.x);
        acc.y = fmaf(wgt, hv.y, acc.y);
        acc.z = fmaf(wgt, hv.z, acc.z);
        acc.w = fmaf(wgt, hv.w, acc.w);
    }

    float inv = (end > start) ? (1.0f / den) : 0.f;
    float4 res;
    res.x = gelu_exact(acc.x * inv);
    res.y = gelu_exact(acc.y * inv);
    res.z = gelu_exact(acc.z * inv);
    res.w = gelu_exact(acc.w * inv);
    *(float4*)&out[(size_t)n * HD + lane * 4] = res;
}

// ---------------- launch: two graph branches ----------------
extern "C" void kernel_launch(void* const* d_in, const int* in_sizes, int n_in,
                              void* d_out, int out_size) {
    const float* x     = (const float*)d_in[0];
    const int*   adj   = (const int*)d_in[1];
    const float* w     = (const float*)d_in[2];
    const float* Wm    = (const float*)d_in[3];
    const float* a_src = (const float*)d_in[4];
    const float* a_dst = (const float*)d_in[5];
    float*       out   = (float*)d_out;

    const int Nn   = in_sizes[0] / DIN;
    const int E    = in_sizes[2];
    const int Npad = ((Nn + 127) / 128) * 128;
    const int NB   = (Nn + 511) / 512;

    cudaFuncSetAttribute(hmma_gemm_kernel,
                         cudaFuncAttributeMaxDynamicSharedMemorySize, SM_TOT);

    // side stream + events (host objects; created per call, intentionally not
    // destroyed — kernel_launch runs only for correctness + capture, and
    // destroying a stream that participated in an ongoing capture is invalid)
    cudaStream_t s2;
    cudaStreamCreateWithFlags(&s2, cudaStreamNonBlocking);
    cudaEvent_t evFork, evJoin;
    cudaEventCreateWithFlags(&evFork, cudaEventDisableTiming);
    cudaEventCreateWithFlags(&evJoin, cudaEventDisableTiming);

    // fork: CSR branch depends only on adj
    cudaEventRecord(evFork, 0);
    cudaStreamWaitEvent(s2, evFork, 0);
    zdeg_kernel<<<(Nn + 256) / 256, 256, 0, s2>>>(Nn);
    hist_kernel<<<(E + 255) / 256, 256, 0, s2>>>((const int2*)adj, E);
    scan1_kernel<<<NB, 512, 0, s2>>>(Nn);
    scan2_kernel<<<1, 128, 0, s2>>>(NB, Nn, E);
    scan3_kernel<<<NB, 512, 0, s2>>>(Nn);
    cudaEventRecord(evJoin, s2);

    // main branch: feature pipeline
    prep_kernel<<<(HD * DIN + 255) / 256, 256>>>(Wm, Nn);
    hmma_gemm_kernel<<<Npad / 128, 256, SM_TOT>>>(x, Nn);
    sdot_kernel<<<(Nn * 32 + 255) / 256, 256>>>((const float4*)a_src,
                                                (const float4*)a_dst, Nn);

    // join: scatter needs sdot (main) + scan3 (side)
    cudaStreamWaitEvent(0, evJoin, 0);
    scatter_kernel<<<(E + 255) / 256, 256>>>((const int2*)adj, w, E);
    aggregate_kernel<<<(Nn * 32 + 255) / 256, 256>>>(out, Nn);
}